// round 7
// baseline (speedup 1.0000x reference)
#include <cuda_runtime.h>
#include <math.h>

// Problem constants (from reference)
#define NN 20000
#define EE 640000
#define HH 4
#define CC 64
#define HC 256   // HH*CC
#define IN1 128  // layer-1 input channels

// ---------------- static device scratch (no allocations allowed) ----------------
__device__ __align__(16) float g_xh[(size_t)NN * HC];   // per-head features of current layer
__device__ __align__(16) float g_h1[(size_t)NN * HC];   // layer-1 output
__device__ float g_asrc[NN * HH];
__device__ float g_adst[NN * HH];
__device__ int   g_deg[NN];
__device__ int   g_cur[NN];
__device__ int   g_rowptr[NN + 1];
__device__ int   g_csr_src[EE];
__device__ int   g_csr_eid[EE];
__device__ float g_ce[2 * HH];

// ---------------- CSR construction ----------------
__global__ void zero_kernel(int n) {
    int i = blockIdx.x * blockDim.x + threadIdx.x;
    if (i < n) { g_deg[i] = 0; g_cur[i] = 0; }
}

__global__ void count_kernel(const int* __restrict__ dst, int E) {
    int e = blockIdx.x * blockDim.x + threadIdx.x;
    if (e < E) atomicAdd(&g_deg[dst[e]], 1);
}

__global__ void scan_kernel(int n, int total) {
    __shared__ int sh[1024];
    int t = threadIdx.x;
    int chunk = (n + 1023) >> 10;
    int beg = t * chunk, end = min(beg + chunk, n);
    int s = 0;
    for (int i = beg; i < end; i++) s += g_deg[i];
    sh[t] = s;
    __syncthreads();
    for (int o = 1; o < 1024; o <<= 1) {
        int v = (t >= o) ? sh[t - o] : 0;
        __syncthreads();
        sh[t] += v;
        __syncthreads();
    }
    int run = (t == 0) ? 0 : sh[t - 1];
    for (int i = beg; i < end; i++) { g_rowptr[i] = run; run += g_deg[i]; }
    if (t == 0) g_rowptr[n] = total;
}

__global__ void fill_kernel(const int* __restrict__ src, const int* __restrict__ dst, int E) {
    int e = blockIdx.x * blockDim.x + threadIdx.x;
    if (e < E) {
        int d = dst[e];
        int pos = atomicAdd(&g_cur[d], 1);
        int idx = g_rowptr[d] + pos;
        g_csr_src[idx] = src[e];
        g_csr_eid[idx] = e;
    }
}

// ---------------- per-head edge-scalar precompute: ce[h] = sum_c W_e[h*C+c]*a_e[h*C+c] ----------------
__global__ void ce_kernel(const float* __restrict__ We1, const float* __restrict__ ae1,
                          const float* __restrict__ We2, const float* __restrict__ ae2) {
    int tid = threadIdx.x;  // 256 threads
    float p1 = We1[tid] * ae1[tid];
    float p2 = We2[tid] * ae2[tid];
    for (int o = 16; o; o >>= 1) {
        p1 += __shfl_xor_sync(0xffffffffu, p1, o);
        p2 += __shfl_xor_sync(0xffffffffu, p2, o);
    }
    __shared__ float s1[8], s2[8];
    int w = tid >> 5;
    if ((tid & 31) == 0) { s1[w] = p1; s2[w] = p2; }
    __syncthreads();
    if (tid < HH) {
        g_ce[tid]      = s1[2 * tid] + s1[2 * tid + 1];
        g_ce[HH + tid] = s2[2 * tid] + s2[2 * tid + 1];
    }
}

// ---------------- alpha_src / alpha_dst per node: dot over C within each head ----------------
__global__ __launch_bounds__(256) void alpha_kernel(const float* __restrict__ xh,
                                                    const float* __restrict__ a_src,
                                                    const float* __restrict__ a_dst) {
    int v = blockIdx.x;
    int tid = threadIdx.x;  // 256 threads; a_src/a_dst are [H,C] flat = 256 floats, same layout as xh row
    float xv = xh[(size_t)v * HC + tid];
    float ps = xv * a_src[tid];
    float pd = xv * a_dst[tid];
    for (int o = 16; o; o >>= 1) {
        ps += __shfl_xor_sync(0xffffffffu, ps, o);
        pd += __shfl_xor_sync(0xffffffffu, pd, o);
    }
    __shared__ float ss[8], sd[8];
    int w = tid >> 5;
    if ((tid & 31) == 0) { ss[w] = ps; sd[w] = pd; }
    __syncthreads();
    if (tid < HH) {
        g_asrc[v * HH + tid] = ss[2 * tid] + ss[2 * tid + 1];
        g_adst[v * HH + tid] = sd[2 * tid] + sd[2 * tid + 1];
    }
}

// ---------------- SGEMM: C[M,N] = A[M,K] @ B[K,N], fp32, N=256 ----------------
#define BM 64
#define BN 64
#define BK 8
__global__ __launch_bounds__(256) void sgemm_kernel(const float* __restrict__ A,
                                                    const float* __restrict__ B,
                                                    float* __restrict__ Cc,
                                                    int M, int N, int K) {
    __shared__ float As[BK][BM];
    __shared__ float Bs[BK][BN];
    int tid = threadIdx.x;
    int tx = tid & 15, ty = tid >> 4;
    int rowBase = blockIdx.y * BM;
    int colBase = blockIdx.x * BN;
    float acc[4][4] = {};
    for (int k0 = 0; k0 < K; k0 += BK) {
#pragma unroll
        for (int l = 0; l < 2; l++) {
            int idx = tid + l * 256;
            int r = idx >> 3, c = idx & 7;
            int row = rowBase + r;
            As[c][r] = (row < M) ? A[(size_t)row * K + k0 + c] : 0.f;
            int rb = idx >> 6, cb = idx & 63;
            Bs[rb][cb] = B[(size_t)(k0 + rb) * N + colBase + cb];
        }
        __syncthreads();
#pragma unroll
        for (int kk = 0; kk < BK; kk++) {
            float4 a4 = *(const float4*)&As[kk][ty * 4];
            float4 b4 = *(const float4*)&Bs[kk][tx * 4];
            float a[4] = {a4.x, a4.y, a4.z, a4.w};
            float b[4] = {b4.x, b4.y, b4.z, b4.w};
#pragma unroll
            for (int i = 0; i < 4; i++)
#pragma unroll
                for (int j = 0; j < 4; j++)
                    acc[i][j] = fmaf(a[i], b[j], acc[i][j]);
        }
        __syncthreads();
    }
#pragma unroll
    for (int i = 0; i < 4; i++) {
        int row = rowBase + ty * 4 + i;
        if (row < M) {
            float4 o4 = make_float4(acc[i][0], acc[i][1], acc[i][2], acc[i][3]);
            *(float4*)&Cc[(size_t)row * N + colBase + tx * 4] = o4;
        }
    }
}

// ---------------- per-dst-node: segment softmax + message aggregation ----------------
// 128 threads = 4 warps; warp w owns head w in every phase.
// Output channels: thread tid owns float2 channels (2*tid, 2*tid+1); head = tid>>5 = warp id.
__global__ __launch_bounds__(128) void node_kernel(const float* __restrict__ xh,
                                                   const float* __restrict__ edge_attr,
                                                   const float* __restrict__ edge_atten,
                                                   const float* __restrict__ bias,
                                                   float* __restrict__ w_out,
                                                   float* __restrict__ out,
                                                   int layer) {
    int v = blockIdx.x;
    int tid = threadIdx.x, lane = tid & 31, h = tid >> 5;
    int start = g_rowptr[v], deg = g_rowptr[v + 1] - start;

    float adst_h = g_adst[v * HH + h];
    float ce_h = g_ce[layer * HH + h];

    // Phase 1: raw alpha (leaky-relu) + warp max. w_out used as scratch.
    float m = -INFINITY;
    for (int j = lane; j < deg; j += 32) {
        int idx = start + j;
        int s = g_csr_src[idx], e = g_csr_eid[idx];
        float raw = g_asrc[s * HH + h] + adst_h + edge_attr[e] * ce_h;
        raw = raw > 0.f ? raw : 0.2f * raw;
        w_out[e * HH + h] = raw;
        m = fmaxf(m, raw);
    }
    for (int o = 16; o; o >>= 1) m = fmaxf(m, __shfl_xor_sync(0xffffffffu, m, o));

    // Phase 2: exp + warp sum (overwrite scratch with exp)
    float ssum = 0.f;
    for (int j = lane; j < deg; j += 32) {
        int e = g_csr_eid[start + j];
        float p = __expf(w_out[e * HH + h] - m);
        w_out[e * HH + h] = p;
        ssum += p;
    }
    for (int o = 16; o; o >>= 1) ssum += __shfl_xor_sync(0xffffffffu, ssum, o);

    __shared__ float sh_inv[HH];
    if (lane == 0) sh_inv[h] = 1.f / (ssum + 1e-16f);
    __syncthreads();

    // Phase 3: chunked aggregation. Per chunk: finalize w, stage scale = w*atten in smem,
    // then all threads accumulate coalesced float2 gathers of xh[src].
    __shared__ float sh_scale[32 * HH];
    __shared__ int sh_src[32];
    float2 acc = make_float2(0.f, 0.f);
    for (int base = 0; base < deg; base += 32) {
        int cnt = min(32, deg - base);
        if (tid < cnt * HH) {
            int j = tid >> 2, hh = tid & 3;   // tid == j*4+hh
            int idx = start + base + j;
            int e = g_csr_eid[idx];
            float wv = w_out[e * HH + hh] * sh_inv[hh];
            w_out[e * HH + hh] = wv;          // final softmax weight output
            sh_scale[tid] = wv * edge_atten[e];
            if (hh == 0) sh_src[j] = g_csr_src[idx];
        }
        __syncthreads();
#pragma unroll 4
        for (int j = 0; j < cnt; j++) {
            float sc = sh_scale[j * HH + h];
            float2 xv = ((const float2*)xh)[(size_t)sh_src[j] * (HC / 2) + tid];
            acc.x = fmaf(sc, xv.x, acc.x);
            acc.y = fmaf(sc, xv.y, acc.y);
        }
        __syncthreads();
    }
    float2 bb = ((const float2*)bias)[tid];
    float2 o2;
    o2.x = acc.x + bb.x;
    o2.y = acc.y + bb.y;
    ((float2*)out)[(size_t)v * (HC / 2) + tid] = o2;
}

// ---------------- launch ----------------
extern "C" void kernel_launch(void* const* d_in, const int* in_sizes, int n_in,
                              void* d_out, int out_size) {
    const float* x         = (const float*)d_in[0];
    const int*   ei        = (const int*)d_in[1];    // [2,E] int32
    const float* edge_attr = (const float*)d_in[3];  // [E,1]
    const float* edge_atten= (const float*)d_in[4];  // [E,1]
    const float* W1     = (const float*)d_in[5];
    const float* a_src1 = (const float*)d_in[6];
    const float* a_dst1 = (const float*)d_in[7];
    const float* W_e1   = (const float*)d_in[8];
    const float* a_e1   = (const float*)d_in[9];
    const float* b1     = (const float*)d_in[10];
    const float* W2     = (const float*)d_in[11];
    const float* a_src2 = (const float*)d_in[12];
    const float* a_dst2 = (const float*)d_in[13];
    const float* W_e2   = (const float*)d_in[14];
    const float* a_e2   = (const float*)d_in[15];
    const float* b2     = (const float*)d_in[16];

    int E  = in_sizes[1] / 2;
    int Nn = in_sizes[0] / IN1;

    const int* src = ei;
    const int* dst = ei + E;

    float* out    = (float*)d_out;
    float* h_out  = out;                              // [N, 256]
    float* w1_out = out + (size_t)Nn * HC;            // [E, 4]
    float* w2_out = w1_out + (size_t)E * HH;          // [E, 4]

    float *p_xh = nullptr, *p_h1 = nullptr;
    cudaGetSymbolAddress((void**)&p_xh, g_xh);
    cudaGetSymbolAddress((void**)&p_h1, g_h1);

    // CSR build (identical for both layers)
    zero_kernel<<<(Nn + 255) / 256, 256>>>(Nn);
    count_kernel<<<(E + 255) / 256, 256>>>(dst, E);
    scan_kernel<<<1, 1024>>>(Nn, E);
    fill_kernel<<<(E + 255) / 256, 256>>>(src, dst, E);
    ce_kernel<<<1, 256>>>(W_e1, a_e1, W_e2, a_e2);

    dim3 gg(HC / BN, (Nn + BM - 1) / BM);

    // Layer 1
    sgemm_kernel<<<gg, 256>>>(x, W1, p_xh, Nn, HC, IN1);
    alpha_kernel<<<Nn, 256>>>(p_xh, a_src1, a_dst1);
    node_kernel<<<Nn, 128>>>(p_xh, edge_attr, edge_atten, b1, w1_out, p_h1, 0);

    // Layer 2
    sgemm_kernel<<<gg, 256>>>(p_h1, W2, p_xh, Nn, HC, HC);
    alpha_kernel<<<Nn, 256>>>(p_xh, a_src2, a_dst2);
    node_kernel<<<Nn, 128>>>(p_xh, edge_attr, edge_atten, b2, w2_out, h_out, 1);
}

// round 8
// speedup vs baseline: 1.3113x; 1.3113x over previous
#include <cuda_runtime.h>
#include <math.h>

// Problem constants (from reference)
#define NN 20000
#define EE 640000
#define HH 4
#define CC 64
#define HC 256   // HH*CC
#define IN1 128  // layer-1 input channels

// ---------------- static device scratch (no allocations allowed) ----------------
__device__ __align__(16) float g_xh[(size_t)NN * HC];   // per-head features of current layer
__device__ __align__(16) float g_h1[(size_t)NN * HC];   // layer-1 output
__device__ float g_asrc[NN * HH];
__device__ float g_adst[NN * HH];
__device__ int   g_deg[NN];
__device__ int   g_cur[NN];
__device__ int   g_rowptr[NN + 1];
__device__ int   g_csr_src[EE];
__device__ int   g_csr_eid[EE];
__device__ float g_ce[2 * HH];

// ---------------- CSR construction ----------------
__global__ void zero_kernel(int n) {
    int i = blockIdx.x * blockDim.x + threadIdx.x;
    if (i < n) { g_deg[i] = 0; g_cur[i] = 0; }
}

__global__ void count_kernel(const int* __restrict__ dst, int E) {
    int e = blockIdx.x * blockDim.x + threadIdx.x;
    if (e < E) atomicAdd(&g_deg[dst[e]], 1);
}

__global__ void scan_kernel(int n, int total) {
    __shared__ int sh[1024];
    int t = threadIdx.x;
    int chunk = (n + 1023) >> 10;
    int beg = t * chunk, end = min(beg + chunk, n);
    int s = 0;
    for (int i = beg; i < end; i++) s += g_deg[i];
    sh[t] = s;
    __syncthreads();
    for (int o = 1; o < 1024; o <<= 1) {
        int v = (t >= o) ? sh[t - o] : 0;
        __syncthreads();
        sh[t] += v;
        __syncthreads();
    }
    int run = (t == 0) ? 0 : sh[t - 1];
    for (int i = beg; i < end; i++) { g_rowptr[i] = run; run += g_deg[i]; }
    if (t == 0) g_rowptr[n] = total;
}

__global__ void fill_kernel(const int* __restrict__ src, const int* __restrict__ dst, int E) {
    int e = blockIdx.x * blockDim.x + threadIdx.x;
    if (e < E) {
        int d = dst[e];
        int pos = atomicAdd(&g_cur[d], 1);
        int idx = g_rowptr[d] + pos;
        g_csr_src[idx] = src[e];
        g_csr_eid[idx] = e;
    }
}

// ---------------- per-head edge-scalar precompute: ce[h] = sum_c W_e[h*C+c]*a_e[h*C+c] ----------------
__global__ void ce_kernel(const float* __restrict__ We1, const float* __restrict__ ae1,
                          const float* __restrict__ We2, const float* __restrict__ ae2) {
    int tid = threadIdx.x;  // 256 threads
    float p1 = We1[tid] * ae1[tid];
    float p2 = We2[tid] * ae2[tid];
    for (int o = 16; o; o >>= 1) {
        p1 += __shfl_xor_sync(0xffffffffu, p1, o);
        p2 += __shfl_xor_sync(0xffffffffu, p2, o);
    }
    __shared__ float s1[8], s2[8];
    int w = tid >> 5;
    if ((tid & 31) == 0) { s1[w] = p1; s2[w] = p2; }
    __syncthreads();
    if (tid < HH) {
        g_ce[tid]      = s1[2 * tid] + s1[2 * tid + 1];
        g_ce[HH + tid] = s2[2 * tid] + s2[2 * tid + 1];
    }
}

// ---------------- alpha_src / alpha_dst per node: dot over C within each head ----------------
__global__ __launch_bounds__(256) void alpha_kernel(const float* __restrict__ xh,
                                                    const float* __restrict__ a_src,
                                                    const float* __restrict__ a_dst) {
    int v = blockIdx.x;
    int tid = threadIdx.x;  // 256 threads; a_src/a_dst are [H,C] flat = 256 floats, same layout as xh row
    float xv = xh[(size_t)v * HC + tid];
    float ps = xv * a_src[tid];
    float pd = xv * a_dst[tid];
    for (int o = 16; o; o >>= 1) {
        ps += __shfl_xor_sync(0xffffffffu, ps, o);
        pd += __shfl_xor_sync(0xffffffffu, pd, o);
    }
    __shared__ float ss[8], sd[8];
    int w = tid >> 5;
    if ((tid & 31) == 0) { ss[w] = ps; sd[w] = pd; }
    __syncthreads();
    if (tid < HH) {
        g_asrc[v * HH + tid] = ss[2 * tid] + ss[2 * tid + 1];
        g_adst[v * HH + tid] = sd[2 * tid] + sd[2 * tid + 1];
    }
}

// ---------------- tf32 tensor-core GEMM: C[M,N] = A[M,K] @ B[K,N] ----------------
// Block tile 128x64, 8 warps (4m x 2n) of 32x32 each, BK=32.
// A smem [m][k] stride 36 (LDS banks (4*grp+tig)%32 -> conflict-free).
// B smem [k][n] stride 72 (LDS banks (8*tig+grp)%32 -> conflict-free).
#define GBM 128
#define GBN 64
#define GBK 32
#define AST 36
#define BST 72

__device__ __forceinline__ unsigned f2tf32(float f) {
    unsigned r;
    asm("cvt.rna.tf32.f32 %0, %1;" : "=r"(r) : "f"(f));
    return r;
}

__device__ __forceinline__ void mma_tf32(float c[4], const unsigned a[4], const unsigned b[2]) {
    asm volatile(
        "mma.sync.aligned.m16n8k8.row.col.f32.tf32.tf32.f32 "
        "{%0,%1,%2,%3}, {%4,%5,%6,%7}, {%8,%9}, {%0,%1,%2,%3};\n"
        : "+f"(c[0]), "+f"(c[1]), "+f"(c[2]), "+f"(c[3])
        : "r"(a[0]), "r"(a[1]), "r"(a[2]), "r"(a[3]), "r"(b[0]), "r"(b[1]));
}

__global__ __launch_bounds__(256, 2) void tf32_gemm_kernel(const float* __restrict__ A,
                                                           const float* __restrict__ B,
                                                           float* __restrict__ C,
                                                           int M, int N, int K) {
    __shared__ unsigned As[GBM * AST];
    __shared__ unsigned Bs[GBK * BST];
    int tid = threadIdx.x;
    int lane = tid & 31, w = tid >> 5;
    int wm = w >> 1, wn = w & 1;
    int tig = lane & 3, grp = lane >> 2;
    int rowBase = blockIdx.y * GBM;
    int colBase = blockIdx.x * GBN;

    // gmem staging coordinates
    int arow = tid >> 3;           // 0..31 (row within 32-row group)
    int acol = (tid & 7) * 4;      // k offset, 0..28
    int brow = tid >> 4;           // 0..15
    int bcol = (tid & 15) * 4;     // 0..60

    float acc[2][4][4];
#pragma unroll
    for (int mt = 0; mt < 2; mt++)
#pragma unroll
        for (int nt = 0; nt < 4; nt++)
#pragma unroll
            for (int i = 0; i < 4; i++) acc[mt][nt][i] = 0.f;

    for (int k0 = 0; k0 < K; k0 += GBK) {
        // stage A (128 x 32), convert to tf32
#pragma unroll
        for (int i = 0; i < 4; i++) {
            int r = arow + 32 * i;
            int gr = rowBase + r;
            float4 v = (gr < M) ? *(const float4*)(A + (size_t)gr * K + k0 + acol)
                                : make_float4(0.f, 0.f, 0.f, 0.f);
            unsigned* p = &As[r * AST + acol];
            p[0] = f2tf32(v.x); p[1] = f2tf32(v.y); p[2] = f2tf32(v.z); p[3] = f2tf32(v.w);
        }
        // stage B (32 x 64), convert to tf32
#pragma unroll
        for (int i = 0; i < 2; i++) {
            int r = brow + 16 * i;
            float4 v = *(const float4*)(B + (size_t)(k0 + r) * N + colBase + bcol);
            unsigned* p = &Bs[r * BST + bcol];
            p[0] = f2tf32(v.x); p[1] = f2tf32(v.y); p[2] = f2tf32(v.z); p[3] = f2tf32(v.w);
        }
        __syncthreads();

#pragma unroll
        for (int kk = 0; kk < GBK; kk += 8) {
            unsigned af[2][4], bf[4][2];
#pragma unroll
            for (int mt = 0; mt < 2; mt++) {
                int m0 = wm * 32 + mt * 16;
                af[mt][0] = As[(m0 + grp) * AST + kk + tig];
                af[mt][1] = As[(m0 + grp + 8) * AST + kk + tig];
                af[mt][2] = As[(m0 + grp) * AST + kk + tig + 4];
                af[mt][3] = As[(m0 + grp + 8) * AST + kk + tig + 4];
            }
#pragma unroll
            for (int nt = 0; nt < 4; nt++) {
                int n0 = wn * 32 + nt * 8;
                bf[nt][0] = Bs[(kk + tig) * BST + n0 + grp];
                bf[nt][1] = Bs[(kk + tig + 4) * BST + n0 + grp];
            }
#pragma unroll
            for (int mt = 0; mt < 2; mt++)
#pragma unroll
                for (int nt = 0; nt < 4; nt++)
                    mma_tf32(acc[mt][nt], af[mt], bf[nt]);
        }
        __syncthreads();
    }

    // epilogue: c0,c1 -> (row grp, cols 2*tig..), c2,c3 -> (row grp+8)
#pragma unroll
    for (int mt = 0; mt < 2; mt++) {
        int r0 = rowBase + wm * 32 + mt * 16 + grp;
#pragma unroll
        for (int half = 0; half < 2; half++) {
            int r = r0 + half * 8;
            if (r < M) {
#pragma unroll
                for (int nt = 0; nt < 4; nt++) {
                    int cidx = colBase + wn * 32 + nt * 8 + tig * 2;
                    float2 o;
                    o.x = acc[mt][nt][half * 2];
                    o.y = acc[mt][nt][half * 2 + 1];
                    *(float2*)(C + (size_t)r * N + cidx) = o;
                }
            }
        }
    }
}

// ---------------- per-dst-node: segment softmax + message aggregation ----------------
// 128 threads = 4 warps; warp w owns head w in every phase.
// Output channels: thread tid owns float2 channels (2*tid, 2*tid+1); head = tid>>5 = warp id.
__global__ __launch_bounds__(128) void node_kernel(const float* __restrict__ xh,
                                                   const float* __restrict__ edge_attr,
                                                   const float* __restrict__ edge_atten,
                                                   const float* __restrict__ bias,
                                                   float* __restrict__ w_out,
                                                   float* __restrict__ out,
                                                   int layer) {
    int v = blockIdx.x;
    int tid = threadIdx.x, lane = tid & 31, h = tid >> 5;
    int start = g_rowptr[v], deg = g_rowptr[v + 1] - start;

    float adst_h = g_adst[v * HH + h];
    float ce_h = g_ce[layer * HH + h];

    // Phase 1: raw alpha (leaky-relu) + warp max. w_out used as scratch.
    float m = -INFINITY;
    for (int j = lane; j < deg; j += 32) {
        int idx = start + j;
        int s = g_csr_src[idx], e = g_csr_eid[idx];
        float raw = g_asrc[s * HH + h] + adst_h + edge_attr[e] * ce_h;
        raw = raw > 0.f ? raw : 0.2f * raw;
        w_out[e * HH + h] = raw;
        m = fmaxf(m, raw);
    }
    for (int o = 16; o; o >>= 1) m = fmaxf(m, __shfl_xor_sync(0xffffffffu, m, o));

    // Phase 2: exp + warp sum (overwrite scratch with exp)
    float ssum = 0.f;
    for (int j = lane; j < deg; j += 32) {
        int e = g_csr_eid[start + j];
        float p = __expf(w_out[e * HH + h] - m);
        w_out[e * HH + h] = p;
        ssum += p;
    }
    for (int o = 16; o; o >>= 1) ssum += __shfl_xor_sync(0xffffffffu, ssum, o);

    __shared__ float sh_inv[HH];
    if (lane == 0) sh_inv[h] = 1.f / (ssum + 1e-16f);
    __syncthreads();

    // Phase 3: chunked aggregation. Per chunk: finalize w, stage scale = w*atten in smem,
    // then all threads accumulate coalesced float2 gathers of xh[src].
    __shared__ float sh_scale[32 * HH];
    __shared__ int sh_src[32];
    float2 acc = make_float2(0.f, 0.f);
    for (int base = 0; base < deg; base += 32) {
        int cnt = min(32, deg - base);
        if (tid < cnt * HH) {
            int j = tid >> 2, hh = tid & 3;   // tid == j*4+hh
            int idx = start + base + j;
            int e = g_csr_eid[idx];
            float wv = w_out[e * HH + hh] * sh_inv[hh];
            w_out[e * HH + hh] = wv;          // final softmax weight output
            sh_scale[tid] = wv * edge_atten[e];
            if (hh == 0) sh_src[j] = g_csr_src[idx];
        }
        __syncthreads();
#pragma unroll 4
        for (int j = 0; j < cnt; j++) {
            float sc = sh_scale[j * HH + h];
            float2 xv = ((const float2*)xh)[(size_t)sh_src[j] * (HC / 2) + tid];
            acc.x = fmaf(sc, xv.x, acc.x);
            acc.y = fmaf(sc, xv.y, acc.y);
        }
        __syncthreads();
    }
    float2 bb = ((const float2*)bias)[tid];
    float2 o2;
    o2.x = acc.x + bb.x;
    o2.y = acc.y + bb.y;
    ((float2*)out)[(size_t)v * (HC / 2) + tid] = o2;
}

// ---------------- launch ----------------
extern "C" void kernel_launch(void* const* d_in, const int* in_sizes, int n_in,
                              void* d_out, int out_size) {
    const float* x         = (const float*)d_in[0];
    const int*   ei        = (const int*)d_in[1];    // [2,E] int32
    const float* edge_attr = (const float*)d_in[3];  // [E,1]
    const float* edge_atten= (const float*)d_in[4];  // [E,1]
    const float* W1     = (const float*)d_in[5];
    const float* a_src1 = (const float*)d_in[6];
    const float* a_dst1 = (const float*)d_in[7];
    const float* W_e1   = (const float*)d_in[8];
    const float* a_e1   = (const float*)d_in[9];
    const float* b1     = (const float*)d_in[10];
    const float* W2     = (const float*)d_in[11];
    const float* a_src2 = (const float*)d_in[12];
    const float* a_dst2 = (const float*)d_in[13];
    const float* W_e2   = (const float*)d_in[14];
    const float* a_e2   = (const float*)d_in[15];
    const float* b2     = (const float*)d_in[16];

    int E  = in_sizes[1] / 2;
    int Nn = in_sizes[0] / IN1;

    const int* src = ei;
    const int* dst = ei + E;

    float* out    = (float*)d_out;
    float* h_out  = out;                              // [N, 256]
    float* w1_out = out + (size_t)Nn * HC;            // [E, 4]
    float* w2_out = w1_out + (size_t)E * HH;          // [E, 4]

    float *p_xh = nullptr, *p_h1 = nullptr;
    cudaGetSymbolAddress((void**)&p_xh, g_xh);
    cudaGetSymbolAddress((void**)&p_h1, g_h1);

    // CSR build (identical for both layers)
    zero_kernel<<<(Nn + 255) / 256, 256>>>(Nn);
    count_kernel<<<(E + 255) / 256, 256>>>(dst, E);
    scan_kernel<<<1, 1024>>>(Nn, E);
    fill_kernel<<<(E + 255) / 256, 256>>>(src, dst, E);
    ce_kernel<<<1, 256>>>(W_e1, a_e1, W_e2, a_e2);

    dim3 gg(HC / GBN, (Nn + GBM - 1) / GBM);

    // Layer 1
    tf32_gemm_kernel<<<gg, 256>>>(x, W1, p_xh, Nn, HC, IN1);
    alpha_kernel<<<Nn, 256>>>(p_xh, a_src1, a_dst1);
    node_kernel<<<Nn, 128>>>(p_xh, edge_attr, edge_atten, b1, w1_out, p_h1, 0);

    // Layer 2
    tf32_gemm_kernel<<<gg, 256>>>(p_h1, W2, p_xh, Nn, HC, HC);
    alpha_kernel<<<Nn, 256>>>(p_xh, a_src2, a_dst2);
    node_kernel<<<Nn, 128>>>(p_xh, edge_attr, edge_atten, b2, w2_out, h_out, 1);
}

// round 10
// speedup vs baseline: 1.7558x; 1.3390x over previous
#include <cuda_runtime.h>
#include <math.h>

// Problem constants (from reference)
#define NN 20000
#define EE 640000
#define HH 4
#define CC 64
#define HC 256   // HH*CC
#define IN1 128  // layer-1 input channels

// ---------------- static device scratch (no allocations allowed) ----------------
__device__ __align__(16) float g_xh[(size_t)NN * HC];   // per-head features of current layer
__device__ __align__(16) float g_h1[(size_t)NN * HC];   // layer-1 output
__device__ float g_asrc[NN * HH];
__device__ float g_adst[NN * HH];
__device__ int   g_deg[NN];
__device__ int   g_cur[NN];
__device__ int   g_rowptr[NN + 1];
__device__ __align__(16) int2 g_csr[EE];                // (src, eid) packed
__device__ float g_ce[2 * HH];

// ---------------- CSR construction ----------------
__global__ void zero_kernel(int n) {
    int i = blockIdx.x * blockDim.x + threadIdx.x;
    if (i < n) g_deg[i] = 0;
}

__global__ void count_kernel(const int* __restrict__ dst, int E) {
    int i = (blockIdx.x * blockDim.x + threadIdx.x) * 4;
    if (i + 3 < E) {
        int4 d = *(const int4*)(dst + i);
        atomicAdd(&g_deg[d.x], 1);
        atomicAdd(&g_deg[d.y], 1);
        atomicAdd(&g_deg[d.z], 1);
        atomicAdd(&g_deg[d.w], 1);
    } else {
        for (int j = i; j < E; j++) atomicAdd(&g_deg[dst[j]], 1);
    }
}

__global__ void scan_kernel(int n, int total) {
    __shared__ int sh[1024];
    int t = threadIdx.x;
    int chunk = (n + 1023) >> 10;
    int beg = t * chunk, end = min(beg + chunk, n);
    int s = 0;
    for (int i = beg; i < end; i++) s += g_deg[i];
    sh[t] = s;
    __syncthreads();
    for (int o = 1; o < 1024; o <<= 1) {
        int v = (t >= o) ? sh[t - o] : 0;
        __syncthreads();
        sh[t] += v;
        __syncthreads();
    }
    int run = (t == 0) ? 0 : sh[t - 1];
    for (int i = beg; i < end; i++) {
        g_rowptr[i] = run;
        run += g_deg[i];
        g_cur[i] = 0;   // fold g_cur zeroing in here (runs before fill)
    }
    if (t == 0) g_rowptr[n] = total;
}

__global__ void fill_kernel(const int* __restrict__ src, const int* __restrict__ dst, int E) {
    int i = (blockIdx.x * blockDim.x + threadIdx.x) * 4;
    if (i + 3 < E) {
        int4 s = *(const int4*)(src + i);
        int4 d = *(const int4*)(dst + i);
        int p;
        p = atomicAdd(&g_cur[d.x], 1); g_csr[g_rowptr[d.x] + p] = make_int2(s.x, i);
        p = atomicAdd(&g_cur[d.y], 1); g_csr[g_rowptr[d.y] + p] = make_int2(s.y, i + 1);
        p = atomicAdd(&g_cur[d.z], 1); g_csr[g_rowptr[d.z] + p] = make_int2(s.z, i + 2);
        p = atomicAdd(&g_cur[d.w], 1); g_csr[g_rowptr[d.w] + p] = make_int2(s.w, i + 3);
    } else {
        for (int j = i; j < E; j++) {
            int dd = dst[j];
            int p = atomicAdd(&g_cur[dd], 1);
            g_csr[g_rowptr[dd] + p] = make_int2(src[j], j);
        }
    }
}

// ---------------- per-head edge-scalar precompute: ce[h] = sum_c W_e[h*C+c]*a_e[h*C+c] ----------------
__global__ void ce_kernel(const float* __restrict__ We1, const float* __restrict__ ae1,
                          const float* __restrict__ We2, const float* __restrict__ ae2) {
    int tid = threadIdx.x;  // 256 threads
    float p1 = We1[tid] * ae1[tid];
    float p2 = We2[tid] * ae2[tid];
    for (int o = 16; o; o >>= 1) {
        p1 += __shfl_xor_sync(0xffffffffu, p1, o);
        p2 += __shfl_xor_sync(0xffffffffu, p2, o);
    }
    __shared__ float s1[8], s2[8];
    int w = tid >> 5;
    if ((tid & 31) == 0) { s1[w] = p1; s2[w] = p2; }
    __syncthreads();
    if (tid < HH) {
        g_ce[tid]      = s1[2 * tid] + s1[2 * tid + 1];
        g_ce[HH + tid] = s2[2 * tid] + s2[2 * tid + 1];
    }
}

// ---------------- tf32 tensor-core GEMM + fused alpha epilogue ----------------
// C[M,N] = A[M,K] @ B[K,N]; block tile 128x64, 8 warps (4m x 2n) of 32x32, BK=32.
// gridDim.x == HH and GBN == CC, so blockIdx.x IS the head -> per-head alpha dots
// (sum over this block's 64 columns of C .* a_src / a_dst) are block-local.
#define GBM 128
#define GBN 64
#define GBK 32
#define AST 36
#define BST 72

__device__ __forceinline__ unsigned f2tf32(float f) {
    unsigned r;
    asm("cvt.rna.tf32.f32 %0, %1;" : "=r"(r) : "f"(f));
    return r;
}

__device__ __forceinline__ void mma_tf32(float c[4], const unsigned a[4], const unsigned b[2]) {
    asm volatile(
        "mma.sync.aligned.m16n8k8.row.col.f32.tf32.tf32.f32 "
        "{%0,%1,%2,%3}, {%4,%5,%6,%7}, {%8,%9}, {%0,%1,%2,%3};\n"
        : "+f"(c[0]), "+f"(c[1]), "+f"(c[2]), "+f"(c[3])
        : "r"(a[0]), "r"(a[1]), "r"(a[2]), "r"(a[3]), "r"(b[0]), "r"(b[1]));
}

__global__ __launch_bounds__(256, 2) void tf32_gemm_kernel(const float* __restrict__ A,
                                                           const float* __restrict__ B,
                                                           float* __restrict__ C,
                                                           const float* __restrict__ Asrc,
                                                           const float* __restrict__ Adst,
                                                           int M, int N, int K) {
    __shared__ unsigned As[GBM * AST];
    __shared__ unsigned Bs[GBK * BST];
    __shared__ float sa[GBM][2];
    __shared__ float sd[GBM][2];
    int tid = threadIdx.x;
    int lane = tid & 31, w = tid >> 5;
    int wm = w >> 1, wn = w & 1;
    int tig = lane & 3, grp = lane >> 2;
    int rowBase = blockIdx.y * GBM;
    int colBase = blockIdx.x * GBN;
    int h = blockIdx.x;   // head (grid.x == HH, GBN == CC)

    // gmem staging coordinates
    int arow = tid >> 3;           // 0..31
    int acol = (tid & 7) * 4;      // 0..28
    int brow = tid >> 4;           // 0..15
    int bcol = (tid & 15) * 4;     // 0..60

    float acc[2][4][4];
#pragma unroll
    for (int mt = 0; mt < 2; mt++)
#pragma unroll
        for (int nt = 0; nt < 4; nt++)
#pragma unroll
            for (int i = 0; i < 4; i++) acc[mt][nt][i] = 0.f;

    float4 ra[4], rb[2];
    // prefetch tile 0
#pragma unroll
    for (int i = 0; i < 4; i++) {
        int gr = rowBase + arow + 32 * i;
        ra[i] = (gr < M) ? *(const float4*)(A + (size_t)gr * K + acol)
                         : make_float4(0.f, 0.f, 0.f, 0.f);
    }
#pragma unroll
    for (int i = 0; i < 2; i++)
        rb[i] = *(const float4*)(B + (size_t)(brow + 16 * i) * N + colBase + bcol);

    int tiles = K / GBK;
    for (int t = 0; t < tiles; t++) {
        // commit prefetched tile to smem (with tf32 conversion)
#pragma unroll
        for (int i = 0; i < 4; i++) {
            unsigned* p = &As[(arow + 32 * i) * AST + acol];
            p[0] = f2tf32(ra[i].x); p[1] = f2tf32(ra[i].y);
            p[2] = f2tf32(ra[i].z); p[3] = f2tf32(ra[i].w);
        }
#pragma unroll
        for (int i = 0; i < 2; i++) {
            unsigned* p = &Bs[(brow + 16 * i) * BST + bcol];
            p[0] = f2tf32(rb[i].x); p[1] = f2tf32(rb[i].y);
            p[2] = f2tf32(rb[i].z); p[3] = f2tf32(rb[i].w);
        }
        __syncthreads();

        // prefetch next tile while computing this one
        if (t + 1 < tiles) {
            int k0 = (t + 1) * GBK;
#pragma unroll
            for (int i = 0; i < 4; i++) {
                int gr = rowBase + arow + 32 * i;
                ra[i] = (gr < M) ? *(const float4*)(A + (size_t)gr * K + k0 + acol)
                                 : make_float4(0.f, 0.f, 0.f, 0.f);
            }
#pragma unroll
            for (int i = 0; i < 2; i++)
                rb[i] = *(const float4*)(B + (size_t)(k0 + brow + 16 * i) * N + colBase + bcol);
        }

#pragma unroll
        for (int kk = 0; kk < GBK; kk += 8) {
            unsigned af[2][4], bf[4][2];
#pragma unroll
            for (int mt = 0; mt < 2; mt++) {
                int m0 = wm * 32 + mt * 16;
                af[mt][0] = As[(m0 + grp) * AST + kk + tig];
                af[mt][1] = As[(m0 + grp + 8) * AST + kk + tig];
                af[mt][2] = As[(m0 + grp) * AST + kk + tig + 4];
                af[mt][3] = As[(m0 + grp + 8) * AST + kk + tig + 4];
            }
#pragma unroll
            for (int nt = 0; nt < 4; nt++) {
                int n0 = wn * 32 + nt * 8;
                bf[nt][0] = Bs[(kk + tig) * BST + n0 + grp];
                bf[nt][1] = Bs[(kk + tig + 4) * BST + n0 + grp];
            }
#pragma unroll
            for (int mt = 0; mt < 2; mt++)
#pragma unroll
                for (int nt = 0; nt < 4; nt++)
                    mma_tf32(acc[mt][nt], af[mt], bf[nt]);
        }
        __syncthreads();
    }

    // epilogue: store C, and fused per-head alpha dots
#pragma unroll
    for (int mt = 0; mt < 2; mt++) {
#pragma unroll
        for (int half = 0; half < 2; half++) {
            int rl = wm * 32 + mt * 16 + grp + half * 8;
            int r = rowBase + rl;
            float s = 0.f, d = 0.f;
#pragma unroll
            for (int nt = 0; nt < 4; nt++) {
#pragma unroll
                for (int j = 0; j < 2; j++) {
                    int lc = wn * 32 + nt * 8 + tig * 2 + j;
                    float v = acc[mt][nt][half * 2 + j];
                    s = fmaf(v, __ldg(Asrc + colBase + lc), s);
                    d = fmaf(v, __ldg(Adst + colBase + lc), d);
                }
            }
            if (r < M) {
#pragma unroll
                for (int nt = 0; nt < 4; nt++) {
                    int cidx = colBase + wn * 32 + nt * 8 + tig * 2;
                    float2 o;
                    o.x = acc[mt][nt][half * 2];
                    o.y = acc[mt][nt][half * 2 + 1];
                    *(float2*)(C + (size_t)r * N + cidx) = o;
                }
            }
            // reduce dot over the 4 tig lanes sharing this row
            s += __shfl_xor_sync(0xffffffffu, s, 1);
            s += __shfl_xor_sync(0xffffffffu, s, 2);
            d += __shfl_xor_sync(0xffffffffu, d, 1);
            d += __shfl_xor_sync(0xffffffffu, d, 2);
            if (tig == 0) { sa[rl][wn] = s; sd[rl][wn] = d; }
        }
    }
    __syncthreads();
    if (tid < GBM) {
        int r = rowBase + tid;
        if (r < M) {
            g_asrc[r * HH + h] = sa[tid][0] + sa[tid][1];
            g_adst[r * HH + h] = sd[tid][0] + sd[tid][1];
        }
    }
}

// ---------------- per-dst-node: register-resident segment softmax + aggregation ----------------
// 128 threads = 4 warps; warp h owns head h. Alpha values held in registers
// (MAXJ=4 per lane -> 128 edges/warp covers Poisson(32) degrees; gmem fallback beyond).
#define MAXJ 4
__global__ __launch_bounds__(128) void node_kernel(const float* __restrict__ xh,
                                                   const float* __restrict__ edge_attr,
                                                   const float* __restrict__ edge_atten,
                                                   const float* __restrict__ bias,
                                                   float* __restrict__ w_out,
                                                   float* __restrict__ out,
                                                   int layer) {
    int v = blockIdx.x;
    int tid = threadIdx.x, lane = tid & 31, h = tid >> 5;
    int start = g_rowptr[v], deg = g_rowptr[v + 1] - start;

    float adst_h = g_adst[v * HH + h];
    float ce_h = g_ce[layer * HH + h];

    float val[MAXJ];
    int esave[MAXJ], ssave[MAXJ];
    int nreg = min(deg, 32 * MAXJ);

    // Phase 1: raw alpha (leaky-relu) into registers; warp max.
    float m = -INFINITY;
#pragma unroll
    for (int k = 0; k < MAXJ; k++) {
        int j = lane + 32 * k;
        if (j < nreg) {
            int2 se = g_csr[start + j];
            float raw = g_asrc[se.x * HH + h] + adst_h + edge_attr[se.y] * ce_h;
            raw = raw > 0.f ? raw : 0.2f * raw;
            val[k] = raw; esave[k] = se.y; ssave[k] = se.x;
            m = fmaxf(m, raw);
        }
    }
    for (int j = lane + 32 * MAXJ; j < deg; j += 32) {   // rare overflow -> gmem scratch
        int2 se = g_csr[start + j];
        float raw = g_asrc[se.x * HH + h] + adst_h + edge_attr[se.y] * ce_h;
        raw = raw > 0.f ? raw : 0.2f * raw;
        w_out[se.y * HH + h] = raw;
        m = fmaxf(m, raw);
    }
    for (int o = 16; o; o >>= 1) m = fmaxf(m, __shfl_xor_sync(0xffffffffu, m, o));

    // Phase 2: exp + warp sum (registers)
    float ssum = 0.f;
#pragma unroll
    for (int k = 0; k < MAXJ; k++) {
        int j = lane + 32 * k;
        if (j < nreg) { float p = __expf(val[k] - m); val[k] = p; ssum += p; }
    }
    for (int j = lane + 32 * MAXJ; j < deg; j += 32) {
        int e = g_csr[start + j].y;
        float p = __expf(w_out[e * HH + h] - m);
        w_out[e * HH + h] = p;
        ssum += p;
    }
    for (int o = 16; o; o >>= 1) ssum += __shfl_xor_sync(0xffffffffu, ssum, o);
    float inv = 1.f / (ssum + 1e-16f);

    // Phase 3: per 32-edge chunk — finalize weights, stage scales, aggregate.
    __shared__ float sh_scale[32 * HH];
    __shared__ int sh_src[32];
    float2 acc = make_float2(0.f, 0.f);
    int nchunk = (deg + 31) >> 5;

#pragma unroll
    for (int c = 0; c < MAXJ; c++) {        // register-resident chunks
        if (c >= nchunk) break;
        int base = c * 32, cnt = min(32, deg - base);
        if (lane < cnt) {
            float wv = val[c] * inv;
            int e = esave[c];
            w_out[e * HH + h] = wv;
            sh_scale[lane * HH + h] = wv * edge_atten[e];
            if (h == 0) sh_src[lane] = ssave[c];
        }
        __syncthreads();
#pragma unroll 4
        for (int j = 0; j < cnt; j++) {
            float sc = sh_scale[j * HH + h];
            float2 xv = ((const float2*)xh)[(size_t)sh_src[j] * (HC / 2) + tid];
            acc.x = fmaf(sc, xv.x, acc.x);
            acc.y = fmaf(sc, xv.y, acc.y);
        }
        __syncthreads();
    }
    for (int c = MAXJ; c < nchunk; c++) {   // overflow chunks (gmem scratch)
        int base = c * 32, cnt = min(32, deg - base);
        if (lane < cnt) {
            int2 se = g_csr[start + base + lane];
            float wv = w_out[se.y * HH + h] * inv;
            w_out[se.y * HH + h] = wv;
            sh_scale[lane * HH + h] = wv * edge_atten[se.y];
            if (h == 0) sh_src[lane] = se.x;
        }
        __syncthreads();
#pragma unroll 4
        for (int j = 0; j < cnt; j++) {
            float sc = sh_scale[j * HH + h];
            float2 xv = ((const float2*)xh)[(size_t)sh_src[j] * (HC / 2) + tid];
            acc.x = fmaf(sc, xv.x, acc.x);
            acc.y = fmaf(sc, xv.y, acc.y);
        }
        __syncthreads();
    }

    float2 bb = ((const float2*)bias)[tid];
    float2 o2;
    o2.x = acc.x + bb.x;
    o2.y = acc.y + bb.y;
    ((float2*)out)[(size_t)v * (HC / 2) + tid] = o2;
}

// ---------------- launch ----------------
extern "C" void kernel_launch(void* const* d_in, const int* in_sizes, int n_in,
                              void* d_out, int out_size) {
    const float* x         = (const float*)d_in[0];
    const int*   ei        = (const int*)d_in[1];    // [2,E] int32
    const float* edge_attr = (const float*)d_in[3];  // [E,1]
    const float* edge_atten= (const float*)d_in[4];  // [E,1]
    const float* W1     = (const float*)d_in[5];
    const float* a_src1 = (const float*)d_in[6];
    const float* a_dst1 = (const float*)d_in[7];
    const float* W_e1   = (const float*)d_in[8];
    const float* a_e1   = (const float*)d_in[9];
    const float* b1     = (const float*)d_in[10];
    const float* W2     = (const float*)d_in[11];
    const float* a_src2 = (const float*)d_in[12];
    const float* a_dst2 = (const float*)d_in[13];
    const float* W_e2   = (const float*)d_in[14];
    const float* a_e2   = (const float*)d_in[15];
    const float* b2     = (const float*)d_in[16];

    int E  = in_sizes[1] / 2;
    int Nn = in_sizes[0] / IN1;

    const int* src = ei;
    const int* dst = ei + E;

    float* out    = (float*)d_out;
    float* h_out  = out;                              // [N, 256]
    float* w1_out = out + (size_t)Nn * HC;            // [E, 4]
    float* w2_out = w1_out + (size_t)E * HH;          // [E, 4]

    float *p_xh = nullptr, *p_h1 = nullptr;
    cudaGetSymbolAddress((void**)&p_xh, g_xh);
    cudaGetSymbolAddress((void**)&p_h1, g_h1);

    // CSR build
    zero_kernel<<<(Nn + 255) / 256, 256>>>(Nn);
    count_kernel<<<(E / 4 + 255) / 256, 256>>>(dst, E);
    scan_kernel<<<1, 1024>>>(Nn, E);
    fill_kernel<<<(E / 4 + 255) / 256, 256>>>(src, dst, E);
    ce_kernel<<<1, 256>>>(W_e1, a_e1, W_e2, a_e2);

    dim3 gg(HC / GBN, (Nn + GBM - 1) / GBM);   // grid.x == HH (one head per col-block)

    // Layer 1 (GEMM computes xh AND alpha_src/alpha_dst)
    tf32_gemm_kernel<<<gg, 256>>>(x, W1, p_xh, a_src1, a_dst1, Nn, HC, IN1);
    node_kernel<<<Nn, 128>>>(p_xh, edge_attr, edge_atten, b1, w1_out, p_h1, 0);

    // Layer 2
    tf32_gemm_kernel<<<gg, 256>>>(p_h1, W2, p_xh, a_src2, a_dst2, Nn, HC, HC);
    node_kernel<<<Nn, 128>>>(p_xh, edge_attr, edge_atten, b2, w2_out, h_out, 1);
}